// round 4
// baseline (speedup 1.0000x reference)
#include <cuda_runtime.h>

// ---------------------------------------------------------------------------
// Attention block: out = proj( MHA( x @ Wqkv^T ) ) + b
//   x:      [2, 2048, 1024] fp32
//   W_qkv:  [3072, 1024]    (torch [out,in]) -> qkv = x @ Wqkv^T
//   W_proj: [1024, 1024]
//   b_proj: [1024]
// Structure: 3 launches
//   1) gemm_qkv_kernel : x @ Wqkv^T, scattered to q/k/v [B,H,N,D], q pre-scaled
//   2) attn_kernel     : flash attention per (b,h), 64x64 tiles, fp32
//   3) gemm_proj_kernel: attn_out @ Wproj^T + bias
// ---------------------------------------------------------------------------

#define DIMC   1024
#define NHEADS 16
#define HDIM   64
#define BATCH  2
#define SEQ    2048
#define QSCALE 0.125f          // 1/sqrt(64)
#define MTOT   (BATCH * SEQ)   // 4096

// -------------------- scratch (device globals; no mallocs) ------------------
__device__ float g_q[(size_t)BATCH * NHEADS * SEQ * HDIM];   // 16 MB
__device__ float g_k[(size_t)BATCH * NHEADS * SEQ * HDIM];   // 16 MB
__device__ float g_v[(size_t)BATCH * NHEADS * SEQ * HDIM];   // 16 MB
__device__ float g_attn[(size_t)BATCH * SEQ * DIMC];         // 16 MB

// -------------------- SGEMM tiling params -----------------------------------
#define BMM  128
#define BKK  16
#define SPAD 132   // 128 + 4 pad: keeps float4 alignment, reduces store conflicts

// ============================================================================
// GEMM 1: qkv = x[4096,1024] @ Wqkv[3072,1024]^T, scatter into q/k/v [B,H,N,D]
// ============================================================================
__global__ __launch_bounds__(256) void gemm_qkv_kernel(
    const float* __restrict__ A, const float* __restrict__ W)
{
    __shared__ float As[BKK][SPAD];   // As[k][m] (transposed)
    __shared__ float Bs[BKK][SPAD];   // Bs[k][n]
    const int K   = DIMC;
    const int tid = threadIdx.x;
    const int m0  = blockIdx.y * BMM;
    const int n0  = blockIdx.x * BMM;
    const int loadRow = tid >> 2;          // 0..63
    const int loadCol = (tid & 3) << 2;    // 0,4,8,12
    const int tr = tid >> 4;               // 0..15 (row group)
    const int tc = tid & 15;               // 0..15 (col group)

    float acc[8][8];
#pragma unroll
    for (int i = 0; i < 8; i++)
#pragma unroll
        for (int j = 0; j < 8; j++) acc[i][j] = 0.f;

    for (int k0 = 0; k0 < K; k0 += BKK) {
        // front-batch all 4 global loads (MLP), then store to smem
        float4 a0g = *(const float4*)&A[(size_t)(m0 + loadRow) * K + k0 + loadCol];
        float4 a1g = *(const float4*)&A[(size_t)(m0 + loadRow + 64) * K + k0 + loadCol];
        float4 b0g = *(const float4*)&W[(size_t)(n0 + loadRow) * K + k0 + loadCol];
        float4 b1g = *(const float4*)&W[(size_t)(n0 + loadRow + 64) * K + k0 + loadCol];
        As[loadCol + 0][loadRow] = a0g.x; As[loadCol + 1][loadRow] = a0g.y;
        As[loadCol + 2][loadRow] = a0g.z; As[loadCol + 3][loadRow] = a0g.w;
        As[loadCol + 0][loadRow + 64] = a1g.x; As[loadCol + 1][loadRow + 64] = a1g.y;
        As[loadCol + 2][loadRow + 64] = a1g.z; As[loadCol + 3][loadRow + 64] = a1g.w;
        Bs[loadCol + 0][loadRow] = b0g.x; Bs[loadCol + 1][loadRow] = b0g.y;
        Bs[loadCol + 2][loadRow] = b0g.z; Bs[loadCol + 3][loadRow] = b0g.w;
        Bs[loadCol + 0][loadRow + 64] = b1g.x; Bs[loadCol + 1][loadRow + 64] = b1g.y;
        Bs[loadCol + 2][loadRow + 64] = b1g.z; Bs[loadCol + 3][loadRow + 64] = b1g.w;
        __syncthreads();
#pragma unroll
        for (int kk = 0; kk < BKK; kk++) {
            float4 a0 = *(const float4*)&As[kk][tr * 8];
            float4 a1 = *(const float4*)&As[kk][tr * 8 + 4];
            float4 b0 = *(const float4*)&Bs[kk][tc * 8];
            float4 b1 = *(const float4*)&Bs[kk][tc * 8 + 4];
            float am[8] = {a0.x, a0.y, a0.z, a0.w, a1.x, a1.y, a1.z, a1.w};
            float bn[8] = {b0.x, b0.y, b0.z, b0.w, b1.x, b1.y, b1.z, b1.w};
#pragma unroll
            for (int i = 0; i < 8; i++)
#pragma unroll
                for (int j = 0; j < 8; j++)
                    acc[i][j] = fmaf(am[i], bn[j], acc[i][j]);
        }
        __syncthreads();
    }

    // epilogue: scatter to q/k/v [B,H,N,D]; q gets QSCALE.
    // Each 8-wide col chunk stays within one (t, head) since 8 | 64 | 1024.
#pragma unroll
    for (int i = 0; i < 8; i++) {
        int row = m0 + tr * 8 + i;
        int b   = row >> 11;           // /2048
        int n   = row & (SEQ - 1);
#pragma unroll
        for (int jj = 0; jj < 8; jj += 4) {
            int col = n0 + tc * 8 + jj;
            int t   = col >> 10;       // 0=q 1=k 2=v
            int rc  = col & 1023;
            int h   = rc >> 6;
            int d   = rc & 63;
            float* dst = (t == 0) ? g_q : (t == 1) ? g_k : g_v;
            float s    = (t == 0) ? QSCALE : 1.f;
            float4 v;
            v.x = acc[i][jj + 0] * s; v.y = acc[i][jj + 1] * s;
            v.z = acc[i][jj + 2] * s; v.w = acc[i][jj + 3] * s;
            *(float4*)&dst[(((size_t)(b * NHEADS + h) * SEQ) + n) * HDIM + d] = v;
        }
    }
}

// ============================================================================
// GEMM 2: out = g_attn[4096,1024] @ Wproj[1024,1024]^T + bias
// ============================================================================
__global__ __launch_bounds__(256) void gemm_proj_kernel(
    const float* __restrict__ W, const float* __restrict__ bias,
    float* __restrict__ out)
{
    __shared__ float As[BKK][SPAD];
    __shared__ float Bs[BKK][SPAD];
    const float* A = g_attn;
    const int K   = DIMC;
    const int tid = threadIdx.x;
    const int m0  = blockIdx.y * BMM;
    const int n0  = blockIdx.x * BMM;
    const int loadRow = tid >> 2;
    const int loadCol = (tid & 3) << 2;
    const int tr = tid >> 4;
    const int tc = tid & 15;

    float acc[8][8];
#pragma unroll
    for (int i = 0; i < 8; i++)
#pragma unroll
        for (int j = 0; j < 8; j++) acc[i][j] = 0.f;

    for (int k0 = 0; k0 < K; k0 += BKK) {
        float4 a0g = *(const float4*)&A[(size_t)(m0 + loadRow) * K + k0 + loadCol];
        float4 a1g = *(const float4*)&A[(size_t)(m0 + loadRow + 64) * K + k0 + loadCol];
        float4 b0g = *(const float4*)&W[(size_t)(n0 + loadRow) * K + k0 + loadCol];
        float4 b1g = *(const float4*)&W[(size_t)(n0 + loadRow + 64) * K + k0 + loadCol];
        As[loadCol + 0][loadRow] = a0g.x; As[loadCol + 1][loadRow] = a0g.y;
        As[loadCol + 2][loadRow] = a0g.z; As[loadCol + 3][loadRow] = a0g.w;
        As[loadCol + 0][loadRow + 64] = a1g.x; As[loadCol + 1][loadRow + 64] = a1g.y;
        As[loadCol + 2][loadRow + 64] = a1g.z; As[loadCol + 3][loadRow + 64] = a1g.w;
        Bs[loadCol + 0][loadRow] = b0g.x; Bs[loadCol + 1][loadRow] = b0g.y;
        Bs[loadCol + 2][loadRow] = b0g.z; Bs[loadCol + 3][loadRow] = b0g.w;
        Bs[loadCol + 0][loadRow + 64] = b1g.x; Bs[loadCol + 1][loadRow + 64] = b1g.y;
        Bs[loadCol + 2][loadRow + 64] = b1g.z; Bs[loadCol + 3][loadRow + 64] = b1g.w;
        __syncthreads();
#pragma unroll
        for (int kk = 0; kk < BKK; kk++) {
            float4 a0 = *(const float4*)&As[kk][tr * 8];
            float4 a1 = *(const float4*)&As[kk][tr * 8 + 4];
            float4 b0 = *(const float4*)&Bs[kk][tc * 8];
            float4 b1 = *(const float4*)&Bs[kk][tc * 8 + 4];
            float am[8] = {a0.x, a0.y, a0.z, a0.w, a1.x, a1.y, a1.z, a1.w};
            float bn[8] = {b0.x, b0.y, b0.z, b0.w, b1.x, b1.y, b1.z, b1.w};
#pragma unroll
            for (int i = 0; i < 8; i++)
#pragma unroll
                for (int j = 0; j < 8; j++)
                    acc[i][j] = fmaf(am[i], bn[j], acc[i][j]);
        }
        __syncthreads();
    }

#pragma unroll
    for (int i = 0; i < 8; i++) {
        int row = m0 + tr * 8 + i;
#pragma unroll
        for (int jj = 0; jj < 8; jj += 4) {
            int col = n0 + tc * 8 + jj;
            float4 bv = *(const float4*)&bias[col];
            float4 v;
            v.x = acc[i][jj + 0] + bv.x; v.y = acc[i][jj + 1] + bv.y;
            v.z = acc[i][jj + 2] + bv.z; v.w = acc[i][jj + 3] + bv.w;
            *(float4*)&out[(size_t)row * DIMC + col] = v;
        }
    }
}

// ============================================================================
// Flash attention: per (b,h), 64-query blocks, loop over 64-key tiles.
// 256 threads = 16x16 grid, each thread owns a 4x4 micro-tile.
// Smem layouts (PAD=68 keeps rows 16B aligned, spreads banks):
//   Qs[d][q], Ks[d][j]  (transposed for contiguous LDS.128 in the S loop)
//   Vs[j][d]            (natural)
//   Ps[j][q]            (P transposed via float4 column-stores)
// ============================================================================
#define FPAD 68
#define SMEM_ATT (4 * 64 * FPAD * sizeof(float))   // 69632 bytes

__device__ __forceinline__ float rmax16(float v) {
    v = fmaxf(v, __shfl_xor_sync(0xffffffffu, v, 1));
    v = fmaxf(v, __shfl_xor_sync(0xffffffffu, v, 2));
    v = fmaxf(v, __shfl_xor_sync(0xffffffffu, v, 4));
    v = fmaxf(v, __shfl_xor_sync(0xffffffffu, v, 8));
    return v;
}
__device__ __forceinline__ float rsum16(float v) {
    v += __shfl_xor_sync(0xffffffffu, v, 1);
    v += __shfl_xor_sync(0xffffffffu, v, 2);
    v += __shfl_xor_sync(0xffffffffu, v, 4);
    v += __shfl_xor_sync(0xffffffffu, v, 8);
    return v;
}

__global__ __launch_bounds__(256) void attn_kernel()
{
    extern __shared__ float smem[];
    float (*Qs)[FPAD] = (float (*)[FPAD])(smem);
    float (*Ks)[FPAD] = (float (*)[FPAD])(smem + 64 * FPAD);
    float (*Vs)[FPAD] = (float (*)[FPAD])(smem + 2 * 64 * FPAD);
    float (*Ps)[FPAD] = (float (*)[FPAD])(smem + 3 * 64 * FPAD);

    const int tid = threadIdx.x;
    const int bh  = blockIdx.y;
    const int q0  = blockIdx.x * 64;
    const float* qp = g_q + (size_t)bh * SEQ * HDIM;
    const float* kp = g_k + (size_t)bh * SEQ * HDIM;
    const float* vp = g_v + (size_t)bh * SEQ * HDIM;
    const int ty  = tid >> 4;          // 0..15: query-row group
    const int tx  = tid & 15;          // 0..15: col group
    const int ty4 = ty << 2;
    const int tx4 = tx << 2;
    const int lr  = tid >> 4;          // load row within pass
    const int lc  = (tid & 15) << 2;   // load d offset (float4)

    // load Q tile transposed: Qs[d][q]
#pragma unroll
    for (int p = 0; p < 4; p++) {
        int q = p * 16 + lr;
        float4 v = *(const float4*)&qp[(size_t)(q0 + q) * HDIM + lc];
        Qs[lc + 0][q] = v.x; Qs[lc + 1][q] = v.y;
        Qs[lc + 2][q] = v.z; Qs[lc + 3][q] = v.w;
    }

    float m[4], l[4], o[4][4];
#pragma unroll
    for (int r = 0; r < 4; r++) {
        m[r] = -1e30f; l[r] = 0.f;
#pragma unroll
        for (int c = 0; c < 4; c++) o[r][c] = 0.f;
    }

    for (int j0 = 0; j0 < SEQ; j0 += 64) {
        __syncthreads();   // prior PV reads of Ks/Vs/Ps done
        // load K transposed + V natural (front-batched global loads)
#pragma unroll
        for (int p = 0; p < 4; p++) {
            int j = p * 16 + lr;
            float4 kv = *(const float4*)&kp[(size_t)(j0 + j) * HDIM + lc];
            float4 vv = *(const float4*)&vp[(size_t)(j0 + j) * HDIM + lc];
            Ks[lc + 0][j] = kv.x; Ks[lc + 1][j] = kv.y;
            Ks[lc + 2][j] = kv.z; Ks[lc + 3][j] = kv.w;
            *(float4*)&Vs[j][lc] = vv;
        }
        __syncthreads();

        // S = Q K^T  (scale folded into q)
        float s[4][4];
#pragma unroll
        for (int r = 0; r < 4; r++)
#pragma unroll
            for (int c = 0; c < 4; c++) s[r][c] = 0.f;
#pragma unroll 8
        for (int kk = 0; kk < HDIM; kk++) {
            float4 qv = *(const float4*)&Qs[kk][ty4];
            float4 kv = *(const float4*)&Ks[kk][tx4];
            float qa[4] = {qv.x, qv.y, qv.z, qv.w};
            float ka[4] = {kv.x, kv.y, kv.z, kv.w};
#pragma unroll
            for (int r = 0; r < 4; r++)
#pragma unroll
                for (int c = 0; c < 4; c++)
                    s[r][c] = fmaf(qa[r], ka[c], s[r][c]);
        }

        // online softmax (row stats replicated across the 16 tx lanes)
#pragma unroll
        for (int r = 0; r < 4; r++) {
            float tm = fmaxf(fmaxf(s[r][0], s[r][1]), fmaxf(s[r][2], s[r][3]));
            tm = rmax16(tm);
            float mn   = fmaxf(m[r], tm);
            float corr = __expf(m[r] - mn);
            float rs = 0.f;
#pragma unroll
            for (int c = 0; c < 4; c++) {
                s[r][c] = __expf(s[r][c] - mn);
                rs += s[r][c];
            }
            rs   = rsum16(rs);
            l[r] = l[r] * corr + rs;
            m[r] = mn;
#pragma unroll
            for (int c = 0; c < 4; c++) o[r][c] *= corr;
        }

        // store P transposed: Ps[j][q] with float4 column stores
#pragma unroll
        for (int c = 0; c < 4; c++) {
            float4 pv;
            pv.x = s[0][c]; pv.y = s[1][c]; pv.z = s[2][c]; pv.w = s[3][c];
            *(float4*)&Ps[tx4 + c][ty4] = pv;
        }
        __syncthreads();

        // O += P V
#pragma unroll 8
        for (int j = 0; j < 64; j++) {
            float4 pv = *(const float4*)&Ps[j][ty4];   // broadcast
            float4 vv = *(const float4*)&Vs[j][tx4];   // contiguous
            float pa[4] = {pv.x, pv.y, pv.z, pv.w};
            float va[4] = {vv.x, vv.y, vv.z, vv.w};
#pragma unroll
            for (int r = 0; r < 4; r++)
#pragma unroll
                for (int c = 0; c < 4; c++)
                    o[r][c] = fmaf(pa[r], va[c], o[r][c]);
        }
    }

    // finalize + write to g_attn in [B, N, H*D] (row-major [4096,1024])
    const int b = bh >> 4;
    const int h = bh & 15;
#pragma unroll
    for (int r = 0; r < 4; r++) {
        float inv = 1.f / l[r];
        int q = q0 + ty4 + r;
        float4 ov;
        ov.x = o[r][0] * inv; ov.y = o[r][1] * inv;
        ov.z = o[r][2] * inv; ov.w = o[r][3] * inv;
        *(float4*)&g_attn[((size_t)b * SEQ + q) * DIMC + h * HDIM + tx4] = ov;
    }
}

// ============================================================================
// launch
// ============================================================================
extern "C" void kernel_launch(void* const* d_in, const int* in_sizes, int n_in,
                              void* d_out, int out_size)
{
    const float* x     = (const float*)d_in[0];
    const float* Wqkv  = (const float*)d_in[1];
    const float* Wproj = (const float*)d_in[2];
    const float* bproj = (const float*)d_in[3];
    float* out = (float*)d_out;

    cudaFuncSetAttribute(attn_kernel,
                         cudaFuncAttributeMaxDynamicSharedMemorySize,
                         (int)SMEM_ATT);

    dim3 blk(256);
    gemm_qkv_kernel<<<dim3(3 * DIMC / BMM, MTOT / BMM), blk>>>(x, Wqkv);   // (24, 32)
    attn_kernel<<<dim3(SEQ / 64, BATCH * NHEADS), blk, SMEM_ATT>>>();      // (32, 32)
    gemm_proj_kernel<<<dim3(DIMC / BMM, MTOT / BMM), blk>>>(Wproj, bproj, out); // (8, 32)
}

// round 6
// speedup vs baseline: 1.1285x; 1.1285x over previous
#include <cuda_runtime.h>
#include <mma.h>
#include <cstdint>

using namespace nvcuda;

// ---------------------------------------------------------------------------
// out = proj( MHA( x @ Wqkv^T ) ) + b
// R5: dense GEMMs on wmma tf32 (tensor pipe via portable mma PTX),
//     flash attention fp32 (unchanged, known-good).
// ---------------------------------------------------------------------------

#define DIMC   1024
#define NHEADS 16
#define HDIM   64
#define BATCH  2
#define SEQ    2048
#define QSCALE 0.125f
#define MTOT   (BATCH * SEQ)

// -------------------- scratch (device globals; no mallocs) ------------------
__device__ float g_q[(size_t)BATCH * NHEADS * SEQ * HDIM];
__device__ float g_k[(size_t)BATCH * NHEADS * SEQ * HDIM];
__device__ float g_v[(size_t)BATCH * NHEADS * SEQ * HDIM];
__device__ float g_attn[(size_t)BATCH * SEQ * DIMC];

// ======================= wmma tf32 GEMM =====================================
// C[M,N] = A[M,K] * W[N,K]^T  (both row-major, K contiguous)
// CTA tile 128x128, BK=32, 512 threads = 16 warps (4x4), warp tile 32x32,
// fragments m16n16k8: a row-major from As[m][k], b col-major from Ws[n][k].
#define BK      32
#define LDS_S   36                         // 32 + 4 pad (144B, mult of 16)
#define BUF_FL  (128 * LDS_S)              // floats per matrix per buffer
#define GEMM_SMEM (2 * 2 * BUF_FL * 4)     // 73728 bytes

using FragA = wmma::fragment<wmma::matrix_a, 16, 16, 8, wmma::precision::tf32, wmma::row_major>;
using FragB = wmma::fragment<wmma::matrix_b, 16, 16, 8, wmma::precision::tf32, wmma::col_major>;
using FragC = wmma::fragment<wmma::accumulator, 16, 16, 8, float>;

__device__ __forceinline__ void cvt_frag_a(FragA& f) {
#pragma unroll
    for (int i = 0; i < f.num_elements; i++) f.x[i] = wmma::__float_to_tf32(f.x[i]);
}
__device__ __forceinline__ void cvt_frag_b(FragB& f) {
#pragma unroll
    for (int i = 0; i < f.num_elements; i++) f.x[i] = wmma::__float_to_tf32(f.x[i]);
}

// Mainloop: accumulates the 128x128 tile into acc[2][2] per warp.
__device__ __forceinline__ void gemm_tf32_mainloop(
    const float* __restrict__ A, const float* __restrict__ W,
    int m0, int n0, float* As, float* Ws, FragC acc[2][2])
{
    const int tid  = threadIdx.x;
    const int row2 = tid >> 3;         // 0..63
    const int c4   = (tid & 7) << 2;   // 0,4,...,28
    const int wid  = tid >> 5;
    const int wm   = (wid >> 2) * 32;  // warp m offset
    const int wn   = (wid & 3) * 32;   // warp n offset

#pragma unroll
    for (int i = 0; i < 2; i++)
#pragma unroll
        for (int j = 0; j < 2; j++) wmma::fill_fragment(acc[i][j], 0.f);

    // prologue: fill buffer 0
#pragma unroll
    for (int p = 0; p < 2; p++) {
        int row = p * 64 + row2;
        float4 av = *(const float4*)&A[(size_t)(m0 + row) * DIMC + c4];
        float4 wv = *(const float4*)&W[(size_t)(n0 + row) * DIMC + c4];
        *(float4*)&As[row * LDS_S + c4] = av;
        *(float4*)&Ws[row * LDS_S + c4] = wv;
    }
    __syncthreads();

    const int KT = DIMC / BK;   // 32
    float4 apre[2], wpre[2];
    for (int kb = 0; kb < KT; kb++) {
        const int cur = kb & 1;
        if (kb + 1 < KT) {
#pragma unroll
            for (int p = 0; p < 2; p++) {
                int row = p * 64 + row2;
                apre[p] = *(const float4*)&A[(size_t)(m0 + row) * DIMC + (kb + 1) * BK + c4];
                wpre[p] = *(const float4*)&W[(size_t)(n0 + row) * DIMC + (kb + 1) * BK + c4];
            }
        }
        const float* as = As + cur * 2 * BUF_FL;   // interleave: A bufs at 0, 2*BUF? see layout below
        const float* ws = Ws + cur * 2 * BUF_FL;
#pragma unroll
        for (int ks = 0; ks < BK / 8; ks++) {
            const int k0 = ks * 8;
            FragA a[2]; FragB b[2];
#pragma unroll
            for (int i = 0; i < 2; i++) {
                wmma::load_matrix_sync(a[i], as + (wm + i * 16) * LDS_S + k0, LDS_S);
                cvt_frag_a(a[i]);
            }
#pragma unroll
            for (int j = 0; j < 2; j++) {
                wmma::load_matrix_sync(b[j], ws + (wn + j * 16) * LDS_S + k0, LDS_S);
                cvt_frag_b(b[j]);
            }
#pragma unroll
            for (int i = 0; i < 2; i++)
#pragma unroll
                for (int j = 0; j < 2; j++)
                    wmma::mma_sync(acc[i][j], a[i], b[j], acc[i][j]);
        }
        if (kb + 1 < KT) {
            float* asn = As + (cur ^ 1) * 2 * BUF_FL;
            float* wsn = Ws + (cur ^ 1) * 2 * BUF_FL;
#pragma unroll
            for (int p = 0; p < 2; p++) {
                int row = p * 64 + row2;
                *(float4*)&asn[row * LDS_S + c4] = apre[p];
                *(float4*)&wsn[row * LDS_S + c4] = wpre[p];
            }
            __syncthreads();
        }
    }
}

// ============================================================================
// GEMM 1: qkv = x @ Wqkv^T, scatter to q/k/v [B,H,N,D], q pre-scaled.
// Each 16x16 output tile lies within one (q|k|v, batch, head) region, so
// fragments store directly to the scattered destination with ld = HDIM.
// ============================================================================
__global__ __launch_bounds__(512) void gemm_qkv_tc(
    const float* __restrict__ A, const float* __restrict__ W)
{
    extern __shared__ float smem[];
    // layout: [buf0 A][buf0 W][buf1 A][buf1 W], each BUF_FL floats
    float* As = smem;               // + cur*2*BUF_FL
    float* Ws = smem + BUF_FL;      // + cur*2*BUF_FL
    const int m0 = blockIdx.y * 128, n0 = blockIdx.x * 128;

    FragC acc[2][2];
    gemm_tf32_mainloop(A, W, m0, n0, As, Ws, acc);

    const int wid = threadIdx.x >> 5;
    const int wm  = (wid >> 2) * 32;
    const int wn  = (wid & 3) * 32;

    const int t = n0 >> 10;                       // 0=q 1=k 2=v (128 | 1024)
    float* dst = (t == 0) ? g_q : ((t == 1) ? g_k : g_v);
    const float scale = (t == 0) ? QSCALE : 1.f;

#pragma unroll
    for (int i = 0; i < 2; i++) {
        int mrow = m0 + wm + i * 16;              // tile rows within one batch
        int bb = mrow >> 11, nn = mrow & (SEQ - 1);
#pragma unroll
        for (int j = 0; j < 2; j++) {
            int col = n0 + wn + j * 16;
            int h = (col & 1023) >> 6, d0 = col & 63;
            if (t == 0) {
#pragma unroll
                for (int e = 0; e < acc[i][j].num_elements; e++)
                    acc[i][j].x[e] *= scale;
            }
            float* p = &dst[(((size_t)(bb * NHEADS + h) * SEQ) + nn) * HDIM + d0];
            wmma::store_matrix_sync(p, acc[i][j], HDIM, wmma::mem_row_major);
        }
    }
}

// ============================================================================
// GEMM 2: out = g_attn @ Wproj^T + bias (smem staging for bias add)
// ============================================================================
__global__ __launch_bounds__(512) void gemm_proj_tc(
    const float* __restrict__ W, const float* __restrict__ bias,
    float* __restrict__ out)
{
    extern __shared__ float smem[];
    float* As = smem;
    float* Ws = smem + BUF_FL;
    const int m0 = blockIdx.y * 128, n0 = blockIdx.x * 128;

    FragC acc[2][2];
    gemm_tf32_mainloop(g_attn, W, m0, n0, As, Ws, acc);

    __syncthreads();   // done reading smem; reuse as staging
    const int tid  = threadIdx.x;
    const int wid  = tid >> 5;
    const int lane = tid & 31;
    const int wm   = (wid >> 2) * 32;
    const int wn   = (wid & 3) * 32;
    float* stg = smem + wid * (32 * LDS_S);   // 32 rows x 36 floats per warp

#pragma unroll
    for (int i = 0; i < 2; i++)
#pragma unroll
        for (int j = 0; j < 2; j++)
            wmma::store_matrix_sync(stg + (i * 16) * LDS_S + j * 16,
                                    acc[i][j], LDS_S, wmma::mem_row_major);
    __syncwarp();

    // 32 rows x 32 cols per warp = 256 float4; 32 lanes -> 8 each
#pragma unroll
    for (int it = 0; it < 8; it++) {
        int idx = it * 32 + lane;          // 0..255
        int r   = idx >> 3;                // 0..31
        int cc  = (idx & 7) << 2;          // 0..28
        int grow = m0 + wm + r;
        int gcol = n0 + wn + cc;
        float4 v = *(float4*)&stg[r * LDS_S + cc];
        float4 bv = *(const float4*)&bias[gcol];
        v.x += bv.x; v.y += bv.y; v.z += bv.z; v.w += bv.w;
        *(float4*)&out[(size_t)grow * DIMC + gcol] = v;
    }
}

// ============================================================================
// Flash attention (unchanged R3): per (b,h), 64x64 tiles, fp32 CUDA cores
// ============================================================================
#define FPAD 68
#define SMEM_ATT (4 * 64 * FPAD * sizeof(float))

__device__ __forceinline__ float rmax16(float v) {
    v = fmaxf(v, __shfl_xor_sync(0xffffffffu, v, 1));
    v = fmaxf(v, __shfl_xor_sync(0xffffffffu, v, 2));
    v = fmaxf(v, __shfl_xor_sync(0xffffffffu, v, 4));
    v = fmaxf(v, __shfl_xor_sync(0xffffffffu, v, 8));
    return v;
}
__device__ __forceinline__ float rsum16(float v) {
    v += __shfl_xor_sync(0xffffffffu, v, 1);
    v += __shfl_xor_sync(0xffffffffu, v, 2);
    v += __shfl_xor_sync(0xffffffffu, v, 4);
    v += __shfl_xor_sync(0xffffffffu, v, 8);
    return v;
}

__global__ __launch_bounds__(256) void attn_kernel()
{
    extern __shared__ float smemf[];
    float (*Qs)[FPAD] = (float (*)[FPAD])(smemf);
    float (*Ks)[FPAD] = (float (*)[FPAD])(smemf + 64 * FPAD);
    float (*Vs)[FPAD] = (float (*)[FPAD])(smemf + 2 * 64 * FPAD);
    float (*Ps)[FPAD] = (float (*)[FPAD])(smemf + 3 * 64 * FPAD);

    const int tid = threadIdx.x;
    const int bh  = blockIdx.y;
    const int q0  = blockIdx.x * 64;
    const float* qp = g_q + (size_t)bh * SEQ * HDIM;
    const float* kp = g_k + (size_t)bh * SEQ * HDIM;
    const float* vp = g_v + (size_t)bh * SEQ * HDIM;
    const int ty  = tid >> 4;
    const int tx  = tid & 15;
    const int ty4 = ty << 2;
    const int tx4 = tx << 2;
    const int lr  = tid >> 4;
    const int lc  = (tid & 15) << 2;

#pragma unroll
    for (int p = 0; p < 4; p++) {
        int q = p * 16 + lr;
        float4 v = *(const float4*)&qp[(size_t)(q0 + q) * HDIM + lc];
        Qs[lc + 0][q] = v.x; Qs[lc + 1][q] = v.y;
        Qs[lc + 2][q] = v.z; Qs[lc + 3][q] = v.w;
    }

    float m[4], l[4], o[4][4];
#pragma unroll
    for (int r = 0; r < 4; r++) {
        m[r] = -1e30f; l[r] = 0.f;
#pragma unroll
        for (int c = 0; c < 4; c++) o[r][c] = 0.f;
    }

    for (int j0 = 0; j0 < SEQ; j0 += 64) {
        __syncthreads();
#pragma unroll
        for (int p = 0; p < 4; p++) {
            int j = p * 16 + lr;
            float4 kv = *(const float4*)&kp[(size_t)(j0 + j) * HDIM + lc];
            float4 vv = *(const float4*)&vp[(size_t)(j0 + j) * HDIM + lc];
            Ks[lc + 0][j] = kv.x; Ks[lc + 1][j] = kv.y;
            Ks[lc + 2][j] = kv.z; Ks[lc + 3][j] = kv.w;
            *(float4*)&Vs[j][lc] = vv;
        }
        __syncthreads();

        float s[4][4];
#pragma unroll
        for (int r = 0; r < 4; r++)
#pragma unroll
            for (int c = 0; c < 4; c++) s[r][c] = 0.f;
#pragma unroll 8
        for (int kk = 0; kk < HDIM; kk++) {
            float4 qv = *(const float4*)&Qs[kk][ty4];
            float4 kv = *(const float4*)&Ks[kk][tx4];
            float qa[4] = {qv.x, qv.y, qv.z, qv.w};
            float ka[4] = {kv.x, kv.y, kv.z, kv.w};
#pragma unroll
            for (int r = 0; r < 4; r++)
#pragma unroll
                for (int c = 0; c < 4; c++)
                    s[r][c] = fmaf(qa[r], ka[c], s[r][c]);
        }

#pragma unroll
        for (int r = 0; r < 4; r++) {
            float tm = fmaxf(fmaxf(s[r][0], s[r][1]), fmaxf(s[r][2], s[r][3]));
            tm = rmax16(tm);
            float mn   = fmaxf(m[r], tm);
            float corr = __expf(m[r] - mn);
            float rs = 0.f;
#pragma unroll
            for (int c = 0; c < 4; c++) {
                s[r][c] = __expf(s[r][c] - mn);
                rs += s[r][c];
            }
            rs   = rsum16(rs);
            l[r] = l[r] * corr + rs;
            m[r] = mn;
#pragma unroll
            for (int c = 0; c < 4; c++) o[r][c] *= corr;
        }

#pragma unroll
        for (int c = 0; c < 4; c++) {
            float4 pv;
            pv.x = s[0][c]; pv.y = s[1][c]; pv.z = s[2][c]; pv.w = s[3][c];
            *(float4*)&Ps[tx4 + c][ty4] = pv;
        }
        __syncthreads();

#pragma unroll 8
        for (int j = 0; j < 64; j++) {
            float4 pv = *(const float4*)&Ps[j][ty4];
            float4 vv = *(const float4*)&Vs[j][tx4];
            float pa[4] = {pv.x, pv.y, pv.z, pv.w};
            float va[4] = {vv.x, vv.y, vv.z, vv.w};
#pragma unroll
            for (int r = 0; r < 4; r++)
#pragma unroll
                for (int c = 0; c < 4; c++)
                    o[r][c] = fmaf(pa[r], va[c], o[r][c]);
        }
    }

    const int b = bh >> 4;
    const int h = bh & 15;
#pragma unroll
    for (int r = 0; r < 4; r++) {
        float inv = 1.f / l[r];
        int q = q0 + ty4 + r;
        float4 ov;
        ov.x = o[r][0] * inv; ov.y = o[r][1] * inv;
        ov.z = o[r][2] * inv; ov.w = o[r][3] * inv;
        *(float4*)&g_attn[((size_t)b * SEQ + q) * DIMC + h * HDIM + tx4] = ov;
    }
}

// ============================================================================
// launch
// ============================================================================
extern "C" void kernel_launch(void* const* d_in, const int* in_sizes, int n_in,
                              void* d_out, int out_size)
{
    const float* x     = (const float*)d_in[0];
    const float* Wqkv  = (const float*)d_in[1];
    const float* Wproj = (const float*)d_in[2];
    const float* bproj = (const float*)d_in[3];
    float* out = (float*)d_out;

    cudaFuncSetAttribute(gemm_qkv_tc,
                         cudaFuncAttributeMaxDynamicSharedMemorySize, GEMM_SMEM);
    cudaFuncSetAttribute(gemm_proj_tc,
                         cudaFuncAttributeMaxDynamicSharedMemorySize, GEMM_SMEM);
    cudaFuncSetAttribute(attn_kernel,
                         cudaFuncAttributeMaxDynamicSharedMemorySize, (int)SMEM_ATT);

    gemm_qkv_tc<<<dim3(3 * DIMC / 128, MTOT / 128), 512, GEMM_SMEM>>>(x, Wqkv);
    attn_kernel<<<dim3(SEQ / 64, BATCH * NHEADS), 256, SMEM_ATT>>>();
    gemm_proj_tc<<<dim3(DIMC / 128, MTOT / 128), 512, GEMM_SMEM>>>(Wproj, bproj, out);
}

// round 11
// speedup vs baseline: 1.9212x; 1.7025x over previous
#include <cuda_runtime.h>
#include <mma.h>
#include <cstdint>

using namespace nvcuda;

// ---------------------------------------------------------------------------
// out = proj( MHA( x @ Wqkv^T ) ) + b
// R6: GEMMs on wmma tf32 (unchanged from R5); flash attention now on raw
//     mma.sync.m16n8k8 tf32 with register-resident online softmax.
// ---------------------------------------------------------------------------

#define DIMC   1024
#define NHEADS 16
#define HDIM   64
#define BATCH  2
#define SEQ    2048
#define QSCALE 0.125f
#define MTOT   (BATCH * SEQ)
#define LOG2E  1.4426950408889634f

__device__ float g_q[(size_t)BATCH * NHEADS * SEQ * HDIM];
__device__ float g_k[(size_t)BATCH * NHEADS * SEQ * HDIM];
__device__ float g_v[(size_t)BATCH * NHEADS * SEQ * HDIM];
__device__ float g_attn[(size_t)BATCH * SEQ * DIMC];

// ======================= small PTX helpers ==================================
__device__ __forceinline__ uint32_t f2tf32(float f) {
    uint32_t u;
    asm("cvt.rna.tf32.f32 %0, %1;" : "=r"(u) : "f"(f));
    return u;
}
__device__ __forceinline__ float ex2(float x) {
    float r;
    asm("ex2.approx.f32 %0, %1;" : "=f"(r) : "f"(x));
    return r;
}
// D += A(16x8) * B(8x8); row.col, tf32 inputs, f32 accum.
__device__ __forceinline__ void mma8(float c[4], const uint32_t a[4],
                                     uint32_t b0, uint32_t b1) {
    asm volatile(
        "mma.sync.aligned.m16n8k8.row.col.f32.tf32.tf32.f32 "
        "{%0,%1,%2,%3}, {%4,%5,%6,%7}, {%8,%9}, {%0,%1,%2,%3};"
        : "+f"(c[0]), "+f"(c[1]), "+f"(c[2]), "+f"(c[3])
        : "r"(a[0]), "r"(a[1]), "r"(a[2]), "r"(a[3]), "r"(b0), "r"(b1));
}

// ======================= wmma tf32 GEMM (unchanged R5) ======================
#define BK      32
#define LDS_S   36
#define BUF_FL  (128 * LDS_S)
#define GEMM_SMEM (2 * 2 * BUF_FL * 4)

using FragA = wmma::fragment<wmma::matrix_a, 16, 16, 8, wmma::precision::tf32, wmma::row_major>;
using FragB = wmma::fragment<wmma::matrix_b, 16, 16, 8, wmma::precision::tf32, wmma::col_major>;
using FragC = wmma::fragment<wmma::accumulator, 16, 16, 8, float>;

__device__ __forceinline__ void cvt_frag_a(FragA& f) {
#pragma unroll
    for (int i = 0; i < f.num_elements; i++) f.x[i] = wmma::__float_to_tf32(f.x[i]);
}
__device__ __forceinline__ void cvt_frag_b(FragB& f) {
#pragma unroll
    for (int i = 0; i < f.num_elements; i++) f.x[i] = wmma::__float_to_tf32(f.x[i]);
}

__device__ __forceinline__ void gemm_tf32_mainloop(
    const float* __restrict__ A, const float* __restrict__ W,
    int m0, int n0, float* As, float* Ws, FragC acc[2][2])
{
    const int tid  = threadIdx.x;
    const int row2 = tid >> 3;
    const int c4   = (tid & 7) << 2;
    const int wid  = tid >> 5;
    const int wm   = (wid >> 2) * 32;
    const int wn   = (wid & 3) * 32;

#pragma unroll
    for (int i = 0; i < 2; i++)
#pragma unroll
        for (int j = 0; j < 2; j++) wmma::fill_fragment(acc[i][j], 0.f);

#pragma unroll
    for (int p = 0; p < 2; p++) {
        int row = p * 64 + row2;
        float4 av = *(const float4*)&A[(size_t)(m0 + row) * DIMC + c4];
        float4 wv = *(const float4*)&W[(size_t)(n0 + row) * DIMC + c4];
        *(float4*)&As[row * LDS_S + c4] = av;
        *(float4*)&Ws[row * LDS_S + c4] = wv;
    }
    __syncthreads();

    const int KT = DIMC / BK;
    float4 apre[2], wpre[2];
    for (int kb = 0; kb < KT; kb++) {
        const int cur = kb & 1;
        if (kb + 1 < KT) {
#pragma unroll
            for (int p = 0; p < 2; p++) {
                int row = p * 64 + row2;
                apre[p] = *(const float4*)&A[(size_t)(m0 + row) * DIMC + (kb + 1) * BK + c4];
                wpre[p] = *(const float4*)&W[(size_t)(n0 + row) * DIMC + (kb + 1) * BK + c4];
            }
        }
        const float* as = As + cur * 2 * BUF_FL;
        const float* ws = Ws + cur * 2 * BUF_FL;
#pragma unroll
        for (int ks = 0; ks < BK / 8; ks++) {
            const int k0 = ks * 8;
            FragA a[2]; FragB b[2];
#pragma unroll
            for (int i = 0; i < 2; i++) {
                wmma::load_matrix_sync(a[i], as + (wm + i * 16) * LDS_S + k0, LDS_S);
                cvt_frag_a(a[i]);
            }
#pragma unroll
            for (int j = 0; j < 2; j++) {
                wmma::load_matrix_sync(b[j], ws + (wn + j * 16) * LDS_S + k0, LDS_S);
                cvt_frag_b(b[j]);
            }
#pragma unroll
            for (int i = 0; i < 2; i++)
#pragma unroll
                for (int j = 0; j < 2; j++)
                    wmma::mma_sync(acc[i][j], a[i], b[j], acc[i][j]);
        }
        if (kb + 1 < KT) {
            float* asn = As + (cur ^ 1) * 2 * BUF_FL;
            float* wsn = Ws + (cur ^ 1) * 2 * BUF_FL;
#pragma unroll
            for (int p = 0; p < 2; p++) {
                int row = p * 64 + row2;
                *(float4*)&asn[row * LDS_S + c4] = apre[p];
                *(float4*)&wsn[row * LDS_S + c4] = wpre[p];
            }
            __syncthreads();
        }
    }
}

__global__ __launch_bounds__(512) void gemm_qkv_tc(
    const float* __restrict__ A, const float* __restrict__ W)
{
    extern __shared__ float smem[];
    float* As = smem;
    float* Ws = smem + BUF_FL;
    const int m0 = blockIdx.y * 128, n0 = blockIdx.x * 128;

    FragC acc[2][2];
    gemm_tf32_mainloop(A, W, m0, n0, As, Ws, acc);

    const int wid = threadIdx.x >> 5;
    const int wm  = (wid >> 2) * 32;
    const int wn  = (wid & 3) * 32;

    const int t = n0 >> 10;
    float* dst = (t == 0) ? g_q : ((t == 1) ? g_k : g_v);
    const float scale = (t == 0) ? QSCALE : 1.f;

#pragma unroll
    for (int i = 0; i < 2; i++) {
        int mrow = m0 + wm + i * 16;
        int bb = mrow >> 11, nn = mrow & (SEQ - 1);
#pragma unroll
        for (int j = 0; j < 2; j++) {
            int col = n0 + wn + j * 16;
            int h = (col & 1023) >> 6, d0 = col & 63;
            if (t == 0) {
#pragma unroll
                for (int e = 0; e < acc[i][j].num_elements; e++)
                    acc[i][j].x[e] *= scale;
            }
            float* p = &dst[(((size_t)(bb * NHEADS + h) * SEQ) + nn) * HDIM + d0];
            wmma::store_matrix_sync(p, acc[i][j], HDIM, wmma::mem_row_major);
        }
    }
}

__global__ __launch_bounds__(512) void gemm_proj_tc(
    const float* __restrict__ W, const float* __restrict__ bias,
    float* __restrict__ out)
{
    extern __shared__ float smem[];
    float* As = smem;
    float* Ws = smem + BUF_FL;
    const int m0 = blockIdx.y * 128, n0 = blockIdx.x * 128;

    FragC acc[2][2];
    gemm_tf32_mainloop(g_attn, W, m0, n0, As, Ws, acc);

    __syncthreads();
    const int tid  = threadIdx.x;
    const int wid  = tid >> 5;
    const int lane = tid & 31;
    const int wm   = (wid >> 2) * 32;
    const int wn   = (wid & 3) * 32;
    float* stg = smem + wid * (32 * LDS_S);

#pragma unroll
    for (int i = 0; i < 2; i++)
#pragma unroll
        for (int j = 0; j < 2; j++)
            wmma::store_matrix_sync(stg + (i * 16) * LDS_S + j * 16,
                                    acc[i][j], LDS_S, wmma::mem_row_major);
    __syncwarp();

#pragma unroll
    for (int it = 0; it < 8; it++) {
        int idx = it * 32 + lane;
        int r   = idx >> 3;
        int cc  = (idx & 7) << 2;
        int grow = m0 + wm + r;
        int gcol = n0 + wn + cc;
        float4 v = *(float4*)&stg[r * LDS_S + cc];
        float4 bv = *(const float4*)&bias[gcol];
        v.x += bv.x; v.y += bv.y; v.z += bv.z; v.w += bv.w;
        *(float4*)&out[(size_t)grow * DIMC + gcol] = v;
    }
}

// ============================================================================
// Tensor-core flash attention: one (b,h) per CTA.y, 128-query tile per CTA.x.
// 8 warps x 16 q-rows. mma.m16n8k8 tf32. lane = g*4 + t (g=group, t=in-group).
//   Frag A (16x8): a0(g, t) a1(g+8, t) a2(g, t+4) a3(g+8, t+4)
//   Frag B (8x8) : b0(k=t, n=g) b1(k=t+4, n=g)
//   Frag C (16x8): c0(g, 2t) c1(g, 2t+1) c2(g+8, 2t) c3(g+8, 2t+1)
// Smem (u32 tf32): Ks[64][68] (key,d), Vt[64][68] (d,key), Ps[128][68]
// ============================================================================
#define APAD 68
#define ATT_SMEM ((64 * APAD + 64 * APAD + 128 * APAD) * 4)   // 69632 B

__global__ __launch_bounds__(256) void attn_tc()
{
    extern __shared__ uint32_t sm[];
    uint32_t* Ks = sm;
    uint32_t* Vt = sm + 64 * APAD;
    uint32_t* Ps = sm + 2 * 64 * APAD;
    float*    Pf = (float*)Ps;

    const int tid  = threadIdx.x;
    const int w    = tid >> 5;
    const int lane = tid & 31;
    const int g    = lane >> 2;
    const int t    = lane & 3;
    const int bh   = blockIdx.y;
    const int q0   = blockIdx.x * 128;
    const float* qp = g_q + (size_t)bh * SEQ * HDIM;
    const float* kp = g_k + (size_t)bh * SEQ * HDIM;
    const float* vp = g_v + (size_t)bh * SEQ * HDIM;

    // ---- stage Q (fp32) into Ps region, then extract A-fragments ----
#pragma unroll
    for (int p = 0; p < 8; p++) {
        int idx = p * 256 + tid;            // 0..2047 = 128 rows x 16 float4
        int row = idx >> 4;
        int c0  = (idx & 15) << 2;
        *(float4*)&Pf[row * APAD + c0] = *(const float4*)&qp[(size_t)(q0 + row) * HDIM + c0];
    }
    __syncthreads();

    const int rlo = w * 16 + g;             // warp-local q rows
    const int rhi = rlo + 8;
    uint32_t qa[8][4];
#pragma unroll
    for (int c = 0; c < 8; c++) {
        qa[c][0] = f2tf32(Pf[rlo * APAD + c * 8 + t] * LOG2E);
        qa[c][1] = f2tf32(Pf[rhi * APAD + c * 8 + t] * LOG2E);
        qa[c][2] = f2tf32(Pf[rlo * APAD + c * 8 + t + 4] * LOG2E);
        qa[c][3] = f2tf32(Pf[rhi * APAD + c * 8 + t + 4] * LOG2E);
    }

    float o[8][4];
#pragma unroll
    for (int nt = 0; nt < 8; nt++)
#pragma unroll
        for (int e = 0; e < 4; e++) o[nt][e] = 0.f;
    float m_lo = -1e30f, m_hi = -1e30f, l_lo = 0.f, l_hi = 0.f;

    for (int j0 = 0; j0 < SEQ; j0 += 64) {
        __syncthreads();   // prior tile's PV reads of Ks/Vt done (also covers Q stage)
        // ---- stage K (natural) + V (transposed), cvt to tf32 ----
        {
            int r = tid >> 2;                       // 0..63 key row
            const float* krow = &kp[(size_t)(j0 + r) * HDIM];
            const float* vrow = &vp[(size_t)(j0 + r) * HDIM];
#pragma unroll
            for (int p = 0; p < 4; p++) {
                int d0 = ((tid & 3) + p * 4) << 2;  // 0..60
                float4 kv = *(const float4*)&krow[d0];
                uint4 ku;
                ku.x = f2tf32(kv.x); ku.y = f2tf32(kv.y);
                ku.z = f2tf32(kv.z); ku.w = f2tf32(kv.w);
                *(uint4*)&Ks[r * APAD + d0] = ku;
                float4 vv = *(const float4*)&vrow[d0];
                Vt[(d0 + 0) * APAD + r] = f2tf32(vv.x);
                Vt[(d0 + 1) * APAD + r] = f2tf32(vv.y);
                Vt[(d0 + 2) * APAD + r] = f2tf32(vv.z);
                Vt[(d0 + 3) * APAD + r] = f2tf32(vv.w);
            }
        }
        __syncthreads();

        // ---- S = Q K^T (log2 domain) ----
        float s[8][4];
#pragma unroll
        for (int nt = 0; nt < 8; nt++)
#pragma unroll
            for (int e = 0; e < 4; e++) s[nt][e] = 0.f;
#pragma unroll
        for (int c = 0; c < 8; c++) {
#pragma unroll
            for (int nt = 0; nt < 8; nt++) {
                uint32_t b0 = Ks[(nt * 8 + g) * APAD + c * 8 + t];
                uint32_t b1 = Ks[(nt * 8 + g) * APAD + c * 8 + t + 4];
                mma8(s[nt], qa[c], b0, b1);
            }
        }

        // ---- online softmax (rows g / g+8; quad = lanes sharing g) ----
        float tl = -1e30f, th = -1e30f;
#pragma unroll
        for (int nt = 0; nt < 8; nt++) {
            tl = fmaxf(tl, fmaxf(s[nt][0], s[nt][1]));
            th = fmaxf(th, fmaxf(s[nt][2], s[nt][3]));
        }
        tl = fmaxf(tl, __shfl_xor_sync(0xffffffffu, tl, 1));
        tl = fmaxf(tl, __shfl_xor_sync(0xffffffffu, tl, 2));
        th = fmaxf(th, __shfl_xor_sync(0xffffffffu, th, 1));
        th = fmaxf(th, __shfl_xor_sync(0xffffffffu, th, 2));
        float mn_lo = fmaxf(m_lo, tl), mn_hi = fmaxf(m_hi, th);
        float cr_lo = ex2(m_lo - mn_lo), cr_hi = ex2(m_hi - mn_hi);

        float rs_lo = 0.f, rs_hi = 0.f;
#pragma unroll
        for (int nt = 0; nt < 8; nt++) {
            uint32_t p0 = f2tf32(ex2(s[nt][0] - mn_lo));
            uint32_t p1 = f2tf32(ex2(s[nt][1] - mn_lo));
            uint32_t p2 = f2tf32(ex2(s[nt][2] - mn_hi));
            uint32_t p3 = f2tf32(ex2(s[nt][3] - mn_hi));
            // sum the tf32-rounded values so normalization matches the MMA
            rs_lo += __uint_as_float(p0) + __uint_as_float(p1);
            rs_hi += __uint_as_float(p2) + __uint_as_float(p3);
            Ps[rlo * APAD + nt * 8 + 2 * t]     = p0;
            Ps[rlo * APAD + nt * 8 + 2 * t + 1] = p1;
            Ps[rhi * APAD + nt * 8 + 2 * t]     = p2;
            Ps[rhi * APAD + nt * 8 + 2 * t + 1] = p3;
        }
        rs_lo += __shfl_xor_sync(0xffffffffu, rs_lo, 1);
        rs_lo += __shfl_xor_sync(0xffffffffu, rs_lo, 2);
        rs_hi += __shfl_xor_sync(0xffffffffu, rs_hi, 1);
        rs_hi += __shfl_xor_sync(0xffffffffu, rs_hi, 2);
        l_lo = l_lo * cr_lo + rs_lo;
        l_hi = l_hi * cr_hi + rs_hi;
        m_lo = mn_lo; m_hi = mn_hi;
#pragma unroll
        for (int nt = 0; nt < 8; nt++) {
            o[nt][0] *= cr_lo; o[nt][1] *= cr_lo;
            o[nt][2] *= cr_hi; o[nt][3] *= cr_hi;
        }
        __syncwarp();   // Ps strip is warp-private

        // ---- P A-fragments ----
        uint32_t pa[8][4];
#pragma unroll
        for (int c = 0; c < 8; c++) {
            pa[c][0] = Ps[rlo * APAD + c * 8 + t];
            pa[c][1] = Ps[rhi * APAD + c * 8 + t];
            pa[c][2] = Ps[rlo * APAD + c * 8 + t + 4];
            pa[c][3] = Ps[rhi * APAD + c * 8 + t + 4];
        }

        // ---- O += P V ----
#pragma unroll
        for (int c = 0; c < 8; c++) {
#pragma unroll
            for (int nt = 0; nt < 8; nt++) {
                uint32_t b0 = Vt[(nt * 8 + g) * APAD + c * 8 + t];
                uint32_t b1 = Vt[(nt * 8 + g) * APAD + c * 8 + t + 4];
                mma8(o[nt], pa[c], b0, b1);
            }
        }
    }

    // ---- finalize: O /= l, write to g_attn [B,N,H*D] ----
    const int b = bh >> 4;
    const int h = bh & 15;
    float inv_lo = 1.f / l_lo, inv_hi = 1.f / l_hi;
    size_t base_lo = ((size_t)b * SEQ + q0 + rlo) * DIMC + h * HDIM;
    size_t base_hi = ((size_t)b * SEQ + q0 + rhi) * DIMC + h * HDIM;
#pragma unroll
    for (int nt = 0; nt < 8; nt++) {
        float2 vlo = make_float2(o[nt][0] * inv_lo, o[nt][1] * inv_lo);
        float2 vhi = make_float2(o[nt][2] * inv_hi, o[nt][3] * inv_hi);
        *(float2*)&g_attn[base_lo + nt * 8 + 2 * t] = vlo;
        *(float2*)&g_attn[base_hi + nt * 8 + 2 * t] = vhi;
    }
}

// ============================================================================
// launch
// ============================================================================
extern "C" void kernel_launch(void* const* d_in, const int* in_sizes, int n_in,
                              void* d_out, int out_size)
{
    const float* x     = (const float*)d_in[0];
    const float* Wqkv  = (const float*)d_in[1];
    const float* Wproj = (const float*)d_in[2];
    const float* bproj = (const float*)d_in[3];
    float* out = (float*)d_out;

    cudaFuncSetAttribute(gemm_qkv_tc,
                         cudaFuncAttributeMaxDynamicSharedMemorySize, GEMM_SMEM);
    cudaFuncSetAttribute(gemm_proj_tc,
                         cudaFuncAttributeMaxDynamicSharedMemorySize, GEMM_SMEM);
    cudaFuncSetAttribute(attn_tc,
                         cudaFuncAttributeMaxDynamicSharedMemorySize, ATT_SMEM);

    gemm_qkv_tc<<<dim3(3 * DIMC / 128, MTOT / 128), 512, GEMM_SMEM>>>(x, Wqkv);
    attn_tc<<<dim3(SEQ / 128, BATCH * NHEADS), 256, ATT_SMEM>>>();
    gemm_proj_tc<<<dim3(DIMC / 128, MTOT / 128), 512, GEMM_SMEM>>>(Wproj, bproj, out);
}

// round 12
// speedup vs baseline: 1.9664x; 1.0235x over previous
#include <cuda_runtime.h>
#include <mma.h>
#include <cstdint>

using namespace nvcuda;

// ---------------------------------------------------------------------------
// out = proj( MHA( x @ Wqkv^T ) ) + b
// R11: GEMMs convert operands to tf32 at smem-staging time (cvt off the
//      MMA critical path; no in-loop cvt). Attention unchanged from R6.
// ---------------------------------------------------------------------------

#define DIMC   1024
#define NHEADS 16
#define HDIM   64
#define BATCH  2
#define SEQ    2048
#define QSCALE 0.125f
#define MTOT   (BATCH * SEQ)
#define LOG2E  1.4426950408889634f

__device__ float g_q[(size_t)BATCH * NHEADS * SEQ * HDIM];
__device__ float g_k[(size_t)BATCH * NHEADS * SEQ * HDIM];
__device__ float g_v[(size_t)BATCH * NHEADS * SEQ * HDIM];
__device__ float g_attn[(size_t)BATCH * SEQ * DIMC];

// ======================= small PTX helpers ==================================
__device__ __forceinline__ uint32_t f2tf32(float f) {
    uint32_t u;
    asm("cvt.rna.tf32.f32 %0, %1;" : "=r"(u) : "f"(f));
    return u;
}
__device__ __forceinline__ float ex2(float x) {
    float r;
    asm("ex2.approx.f32 %0, %1;" : "=f"(r) : "f"(x));
    return r;
}
__device__ __forceinline__ float4 cvt4(float4 v) {
    float4 r;
    r.x = __uint_as_float(f2tf32(v.x));
    r.y = __uint_as_float(f2tf32(v.y));
    r.z = __uint_as_float(f2tf32(v.z));
    r.w = __uint_as_float(f2tf32(v.w));
    return r;
}
// D += A(16x8) * B(8x8); row.col, tf32 inputs, f32 accum.
__device__ __forceinline__ void mma8(float c[4], const uint32_t a[4],
                                     uint32_t b0, uint32_t b1) {
    asm volatile(
        "mma.sync.aligned.m16n8k8.row.col.f32.tf32.tf32.f32 "
        "{%0,%1,%2,%3}, {%4,%5,%6,%7}, {%8,%9}, {%0,%1,%2,%3};"
        : "+f"(c[0]), "+f"(c[1]), "+f"(c[2]), "+f"(c[3])
        : "r"(a[0]), "r"(a[1]), "r"(a[2]), "r"(a[3]), "r"(b0), "r"(b1));
}

// ======================= wmma tf32 GEMM =====================================
// CTA 128x128, BK=32, 512 thr / 16 warps, warp tile 32x32 (2x2 m16n16k8).
// Operands are tf32-rounded at staging; fragments load with no conversion.
#define BK      32
#define LDS_S   36
#define BUF_FL  (128 * LDS_S)
#define GEMM_SMEM (2 * 2 * BUF_FL * 4)

using FragA = wmma::fragment<wmma::matrix_a, 16, 16, 8, wmma::precision::tf32, wmma::row_major>;
using FragB = wmma::fragment<wmma::matrix_b, 16, 16, 8, wmma::precision::tf32, wmma::col_major>;
using FragC = wmma::fragment<wmma::accumulator, 16, 16, 8, float>;

__device__ __forceinline__ void gemm_tf32_mainloop(
    const float* __restrict__ A, const float* __restrict__ W,
    int m0, int n0, float* As, float* Ws, FragC acc[2][2])
{
    const int tid  = threadIdx.x;
    const int row2 = tid >> 3;
    const int c4   = (tid & 7) << 2;
    const int wid  = tid >> 5;
    const int wm   = (wid >> 2) * 32;
    const int wn   = (wid & 3) * 32;

#pragma unroll
    for (int i = 0; i < 2; i++)
#pragma unroll
        for (int j = 0; j < 2; j++) wmma::fill_fragment(acc[i][j], 0.f);

    // prologue: fill buffer 0 (tf32-rounded)
#pragma unroll
    for (int p = 0; p < 2; p++) {
        int row = p * 64 + row2;
        float4 av = *(const float4*)&A[(size_t)(m0 + row) * DIMC + c4];
        float4 wv = *(const float4*)&W[(size_t)(n0 + row) * DIMC + c4];
        *(float4*)&As[row * LDS_S + c4] = cvt4(av);
        *(float4*)&Ws[row * LDS_S + c4] = cvt4(wv);
    }
    __syncthreads();

    const int KT = DIMC / BK;
    float4 apre[2], wpre[2];
    for (int kb = 0; kb < KT; kb++) {
        const int cur = kb & 1;
        if (kb + 1 < KT) {
#pragma unroll
            for (int p = 0; p < 2; p++) {
                int row = p * 64 + row2;
                apre[p] = *(const float4*)&A[(size_t)(m0 + row) * DIMC + (kb + 1) * BK + c4];
                wpre[p] = *(const float4*)&W[(size_t)(n0 + row) * DIMC + (kb + 1) * BK + c4];
            }
        }
        const float* as = As + cur * 2 * BUF_FL;
        const float* ws = Ws + cur * 2 * BUF_FL;
#pragma unroll
        for (int ks = 0; ks < BK / 8; ks++) {
            const int k0 = ks * 8;
            FragA a[2]; FragB b[2];
#pragma unroll
            for (int i = 0; i < 2; i++)
                wmma::load_matrix_sync(a[i], as + (wm + i * 16) * LDS_S + k0, LDS_S);
#pragma unroll
            for (int j = 0; j < 2; j++)
                wmma::load_matrix_sync(b[j], ws + (wn + j * 16) * LDS_S + k0, LDS_S);
#pragma unroll
            for (int i = 0; i < 2; i++)
#pragma unroll
                for (int j = 0; j < 2; j++)
                    wmma::mma_sync(acc[i][j], a[i], b[j], acc[i][j]);
        }
        if (kb + 1 < KT) {
            float* asn = As + (cur ^ 1) * 2 * BUF_FL;
            float* wsn = Ws + (cur ^ 1) * 2 * BUF_FL;
#pragma unroll
            for (int p = 0; p < 2; p++) {
                int row = p * 64 + row2;
                *(float4*)&asn[row * LDS_S + c4] = cvt4(apre[p]);
                *(float4*)&wsn[row * LDS_S + c4] = cvt4(wpre[p]);
            }
            __syncthreads();
        }
    }
}

__global__ __launch_bounds__(512) void gemm_qkv_tc(
    const float* __restrict__ A, const float* __restrict__ W)
{
    extern __shared__ float smem[];
    float* As = smem;
    float* Ws = smem + BUF_FL;
    const int m0 = blockIdx.y * 128, n0 = blockIdx.x * 128;

    FragC acc[2][2];
    gemm_tf32_mainloop(A, W, m0, n0, As, Ws, acc);

    const int wid = threadIdx.x >> 5;
    const int wm  = (wid >> 2) * 32;
    const int wn  = (wid & 3) * 32;

    const int t = n0 >> 10;
    float* dst = (t == 0) ? g_q : ((t == 1) ? g_k : g_v);

#pragma unroll
    for (int i = 0; i < 2; i++) {
        int mrow = m0 + wm + i * 16;
        int bb = mrow >> 11, nn = mrow & (SEQ - 1);
#pragma unroll
        for (int j = 0; j < 2; j++) {
            int col = n0 + wn + j * 16;
            int h = (col & 1023) >> 6, d0 = col & 63;
            if (t == 0) {
#pragma unroll
                for (int e = 0; e < acc[i][j].num_elements; e++)
                    acc[i][j].x[e] *= QSCALE;
            }
            float* p = &dst[(((size_t)(bb * NHEADS + h) * SEQ) + nn) * HDIM + d0];
            wmma::store_matrix_sync(p, acc[i][j], HDIM, wmma::mem_row_major);
        }
    }
}

__global__ __launch_bounds__(512) void gemm_proj_tc(
    const float* __restrict__ W, const float* __restrict__ bias,
    float* __restrict__ out)
{
    extern __shared__ float smem[];
    float* As = smem;
    float* Ws = smem + BUF_FL;
    const int m0 = blockIdx.y * 128, n0 = blockIdx.x * 128;

    FragC acc[2][2];
    gemm_tf32_mainloop(g_attn, W, m0, n0, As, Ws, acc);

    __syncthreads();
    const int tid  = threadIdx.x;
    const int wid  = tid >> 5;
    const int lane = tid & 31;
    const int wm   = (wid >> 2) * 32;
    const int wn   = (wid & 3) * 32;
    float* stg = smem + wid * (32 * LDS_S);

#pragma unroll
    for (int i = 0; i < 2; i++)
#pragma unroll
        for (int j = 0; j < 2; j++)
            wmma::store_matrix_sync(stg + (i * 16) * LDS_S + j * 16,
                                    acc[i][j], LDS_S, wmma::mem_row_major);
    __syncwarp();

#pragma unroll
    for (int it = 0; it < 8; it++) {
        int idx = it * 32 + lane;
        int r   = idx >> 3;
        int cc  = (idx & 7) << 2;
        int grow = m0 + wm + r;
        int gcol = n0 + wn + cc;
        float4 v = *(float4*)&stg[r * LDS_S + cc];
        float4 bv = *(const float4*)&bias[gcol];
        v.x += bv.x; v.y += bv.y; v.z += bv.z; v.w += bv.w;
        *(float4*)&out[(size_t)grow * DIMC + gcol] = v;
    }
}

// ============================================================================
// Tensor-core flash attention (unchanged from R6 — known-good).
// ============================================================================
#define APAD 68
#define ATT_SMEM ((64 * APAD + 64 * APAD + 128 * APAD) * 4)   // 69632 B

__global__ __launch_bounds__(256) void attn_tc()
{
    extern __shared__ uint32_t sm[];
    uint32_t* Ks = sm;
    uint32_t* Vt = sm + 64 * APAD;
    uint32_t* Ps = sm + 2 * 64 * APAD;
    float*    Pf = (float*)Ps;

    const int tid  = threadIdx.x;
    const int w    = tid >> 5;
    const int lane = tid & 31;
    const int g    = lane >> 2;
    const int t    = lane & 3;
    const int bh   = blockIdx.y;
    const int q0   = blockIdx.x * 128;
    const float* qp = g_q + (size_t)bh * SEQ * HDIM;
    const float* kp = g_k + (size_t)bh * SEQ * HDIM;
    const float* vp = g_v + (size_t)bh * SEQ * HDIM;

#pragma unroll
    for (int p = 0; p < 8; p++) {
        int idx = p * 256 + tid;
        int row = idx >> 4;
        int c0  = (idx & 15) << 2;
        *(float4*)&Pf[row * APAD + c0] = *(const float4*)&qp[(size_t)(q0 + row) * HDIM + c0];
    }
    __syncthreads();

    const int rlo = w * 16 + g;
    const int rhi = rlo + 8;
    uint32_t qa[8][4];
#pragma unroll
    for (int c = 0; c < 8; c++) {
        qa[c][0] = f2tf32(Pf[rlo * APAD + c * 8 + t] * LOG2E);
        qa[c][1] = f2tf32(Pf[rhi * APAD + c * 8 + t] * LOG2E);
        qa[c][2] = f2tf32(Pf[rlo * APAD + c * 8 + t + 4] * LOG2E);
        qa[c][3] = f2tf32(Pf[rhi * APAD + c * 8 + t + 4] * LOG2E);
    }

    float o[8][4];
#pragma unroll
    for (int nt = 0; nt < 8; nt++)
#pragma unroll
        for (int e = 0; e < 4; e++) o[nt][e] = 0.f;
    float m_lo = -1e30f, m_hi = -1e30f, l_lo = 0.f, l_hi = 0.f;

    for (int j0 = 0; j0 < SEQ; j0 += 64) {
        __syncthreads();
        {
            int r = tid >> 2;
            const float* krow = &kp[(size_t)(j0 + r) * HDIM];
            const float* vrow = &vp[(size_t)(j0 + r) * HDIM];
#pragma unroll
            for (int p = 0; p < 4; p++) {
                int d0 = ((tid & 3) + p * 4) << 2;
                float4 kv = *(const float4*)&krow[d0];
                uint4 ku;
                ku.x = f2tf32(kv.x); ku.y = f2tf32(kv.y);
                ku.z = f2tf32(kv.z); ku.w = f2tf32(kv.w);
                *(uint4*)&Ks[r * APAD + d0] = ku;
                float4 vv = *(const float4*)&vrow[d0];
                Vt[(d0 + 0) * APAD + r] = f2tf32(vv.x);
                Vt[(d0 + 1) * APAD + r] = f2tf32(vv.y);
                Vt[(d0 + 2) * APAD + r] = f2tf32(vv.z);
                Vt[(d0 + 3) * APAD + r] = f2tf32(vv.w);
            }
        }
        __syncthreads();

        float s[8][4];
#pragma unroll
        for (int nt = 0; nt < 8; nt++)
#pragma unroll
            for (int e = 0; e < 4; e++) s[nt][e] = 0.f;
#pragma unroll
        for (int c = 0; c < 8; c++) {
#pragma unroll
            for (int nt = 0; nt < 8; nt++) {
                uint32_t b0 = Ks[(nt * 8 + g) * APAD + c * 8 + t];
                uint32_t b1 = Ks[(nt * 8 + g) * APAD + c * 8 + t + 4];
                mma8(s[nt], qa[c], b0, b1);
            }
        }

        float tl = -1e30f, th = -1e30f;
#pragma unroll
        for (int nt = 0; nt < 8; nt++) {
            tl = fmaxf(tl, fmaxf(s[nt][0], s[nt][1]));
            th = fmaxf(th, fmaxf(s[nt][2], s[nt][3]));
        }
        tl = fmaxf(tl, __shfl_xor_sync(0xffffffffu, tl, 1));
        tl = fmaxf(tl, __shfl_xor_sync(0xffffffffu, tl, 2));
        th = fmaxf(th, __shfl_xor_sync(0xffffffffu, th, 1));
        th = fmaxf(th, __shfl_xor_sync(0xffffffffu, th, 2));
        float mn_lo = fmaxf(m_lo, tl), mn_hi = fmaxf(m_hi, th);
        float cr_lo = ex2(m_lo - mn_lo), cr_hi = ex2(m_hi - mn_hi);

        float rs_lo = 0.f, rs_hi = 0.f;
#pragma unroll
        for (int nt = 0; nt < 8; nt++) {
            uint32_t p0 = f2tf32(ex2(s[nt][0] - mn_lo));
            uint32_t p1 = f2tf32(ex2(s[nt][1] - mn_lo));
            uint32_t p2 = f2tf32(ex2(s[nt][2] - mn_hi));
            uint32_t p3 = f2tf32(ex2(s[nt][3] - mn_hi));
            rs_lo += __uint_as_float(p0) + __uint_as_float(p1);
            rs_hi += __uint_as_float(p2) + __uint_as_float(p3);
            Ps[rlo * APAD + nt * 8 + 2 * t]     = p0;
            Ps[rlo * APAD + nt * 8 + 2 * t + 1] = p1;
            Ps[rhi * APAD + nt * 8 + 2 * t]     = p2;
            Ps[rhi * APAD + nt * 8 + 2 * t + 1] = p3;
        }
        rs_lo += __shfl_xor_sync(0xffffffffu, rs_lo, 1);
        rs_lo += __shfl_xor_sync(0xffffffffu, rs_lo, 2);
        rs_hi += __shfl_xor_sync(0xffffffffu, rs_hi, 1);
        rs_hi += __shfl_xor_sync(0xffffffffu, rs_hi, 2);
        l_lo = l_lo * cr_lo + rs_lo;
        l_hi = l_hi * cr_hi + rs_hi;
        m_lo = mn_lo; m_hi = mn_hi;
#pragma unroll
        for (int nt = 0; nt < 8; nt++) {
            o[nt][0] *= cr_lo; o[nt][1] *= cr_lo;
            o[nt][2] *= cr_hi; o[nt][3] *= cr_hi;
        }
        __syncwarp();

        uint32_t pa[8][4];
#pragma unroll
        for (int c = 0; c < 8; c++) {
            pa[c][0] = Ps[rlo * APAD + c * 8 + t];
            pa[c][1] = Ps[rhi * APAD + c * 8 + t];
            pa[c][2] = Ps[rlo * APAD + c * 8 + t + 4];
            pa[c][3] = Ps[rhi * APAD + c * 8 + t + 4];
        }

#pragma unroll
        for (int c = 0; c < 8; c++) {
#pragma unroll
            for (int nt = 0; nt < 8; nt++) {
                uint32_t b0 = Vt[(nt * 8 + g) * APAD + c * 8 + t];
                uint32_t b1 = Vt[(nt * 8 + g) * APAD + c * 8 + t + 4];
                mma8(o[nt], pa[c], b0, b1);
            }
        }
    }

    const int b = bh >> 4;
    const int h = bh & 15;
    float inv_lo = 1.f / l_lo, inv_hi = 1.f / l_hi;
    size_t base_lo = ((size_t)b * SEQ + q0 + rlo) * DIMC + h * HDIM;
    size_t base_hi = ((size_t)b * SEQ + q0 + rhi) * DIMC + h * HDIM;
#pragma unroll
    for (int nt = 0; nt < 8; nt++) {
        float2 vlo = make_float2(o[nt][0] * inv_lo, o[nt][1] * inv_lo);
        float2 vhi = make_float2(o[nt][2] * inv_hi, o[nt][3] * inv_hi);
        *(float2*)&g_attn[base_lo + nt * 8 + 2 * t] = vlo;
        *(float2*)&g_attn[base_hi + nt * 8 + 2 * t] = vhi;
    }
}

// ============================================================================
// launch
// ============================================================================
extern "C" void kernel_launch(void* const* d_in, const int* in_sizes, int n_in,
                              void* d_out, int out_size)
{
    const float* x     = (const float*)d_in[0];
    const float* Wqkv  = (const float*)d_in[1];
    const float* Wproj = (const float*)d_in[2];
    const float* bproj = (const float*)d_in[3];
    float* out = (float*)d_out;

    cudaFuncSetAttribute(gemm_qkv_tc,
                         cudaFuncAttributeMaxDynamicSharedMemorySize, GEMM_SMEM);
    cudaFuncSetAttribute(gemm_proj_tc,
                         cudaFuncAttributeMaxDynamicSharedMemorySize, GEMM_SMEM);
    cudaFuncSetAttribute(attn_tc,
                         cudaFuncAttributeMaxDynamicSharedMemorySize, ATT_SMEM);

    gemm_qkv_tc<<<dim3(3 * DIMC / 128, MTOT / 128), 512, GEMM_SMEM>>>(x, Wqkv);
    attn_tc<<<dim3(SEQ / 128, BATCH * NHEADS), 256, ATT_SMEM>>>();
    gemm_proj_tc<<<dim3(DIMC / 128, MTOT / 128), 512, GEMM_SMEM>>>(Wproj, bproj, out);
}

// round 14
// speedup vs baseline: 2.1862x; 1.1118x over previous
#include <cuda_runtime.h>
#include <mma.h>
#include <cstdint>

using namespace nvcuda;

// ---------------------------------------------------------------------------
// out = proj( MHA( x @ Wqkv^T ) ) + b
// R12: GEMMs restructured: 256 thr / 8 warps, 64x32 warp tiles (2 CTAs/SM),
//      cp.async double-buffered staging. Attention unchanged (R6 known-good).
// ---------------------------------------------------------------------------

#define DIMC   1024
#define NHEADS 16
#define HDIM   64
#define BATCH  2
#define SEQ    2048
#define QSCALE 0.125f
#define MTOT   (BATCH * SEQ)
#define LOG2E  1.4426950408889634f

__device__ float g_q[(size_t)BATCH * NHEADS * SEQ * HDIM];
__device__ float g_k[(size_t)BATCH * NHEADS * SEQ * HDIM];
__device__ float g_v[(size_t)BATCH * NHEADS * SEQ * HDIM];
__device__ float g_attn[(size_t)BATCH * SEQ * DIMC];

// ======================= small PTX helpers ==================================
__device__ __forceinline__ uint32_t smem_u32(const void* p) {
    uint32_t a;
    asm("{ .reg .u64 t; cvta.to.shared.u64 t, %1; cvt.u32.u64 %0, t; }"
        : "=r"(a) : "l"(p));
    return a;
}
__device__ __forceinline__ uint32_t f2tf32(float f) {
    uint32_t u;
    asm("cvt.rna.tf32.f32 %0, %1;" : "=r"(u) : "f"(f));
    return u;
}
__device__ __forceinline__ float ex2(float x) {
    float r;
    asm("ex2.approx.f32 %0, %1;" : "=f"(r) : "f"(x));
    return r;
}
#define CP_ASYNC16(dst, src) \
    asm volatile("cp.async.cg.shared.global [%0], [%1], 16;" \
                 :: "r"(dst), "l"(src) : "memory")
#define CP_COMMIT() asm volatile("cp.async.commit_group;" ::: "memory")
#define CP_WAIT(n)  asm volatile("cp.async.wait_group %0;" :: "n"(n) : "memory")

// D += A(16x8) * B(8x8); row.col, tf32 inputs, f32 accum.
__device__ __forceinline__ void mma8(float c[4], const uint32_t a[4],
                                     uint32_t b0, uint32_t b1) {
    asm volatile(
        "mma.sync.aligned.m16n8k8.row.col.f32.tf32.tf32.f32 "
        "{%0,%1,%2,%3}, {%4,%5,%6,%7}, {%8,%9}, {%0,%1,%2,%3};"
        : "+f"(c[0]), "+f"(c[1]), "+f"(c[2]), "+f"(c[3])
        : "r"(a[0]), "r"(a[1]), "r"(a[2]), "r"(a[3]), "r"(b0), "r"(b1));
}

// ======================= wmma tf32 GEMM =====================================
// CTA tile 128x128, BK=32, 256 thr / 8 warps (2x4), warp tile 64x32
// (4x2 m16n16k8 frags). cp.async double-buffered smem; cvt in-loop.
#define BK      32
#define LDS_S   36
#define BUF_FL  (128 * LDS_S)                // floats per matrix per buffer
#define GEMM_SMEM (2 * 2 * BUF_FL * 4)       // 73728 B

using FragA = wmma::fragment<wmma::matrix_a, 16, 16, 8, wmma::precision::tf32, wmma::row_major>;
using FragB = wmma::fragment<wmma::matrix_b, 16, 16, 8, wmma::precision::tf32, wmma::col_major>;
using FragC = wmma::fragment<wmma::accumulator, 16, 16, 8, float>;

__device__ __forceinline__ void cvt_frag_a(FragA& f) {
#pragma unroll
    for (int i = 0; i < f.num_elements; i++) f.x[i] = wmma::__float_to_tf32(f.x[i]);
}
__device__ __forceinline__ void cvt_frag_b(FragB& f) {
#pragma unroll
    for (int i = 0; i < f.num_elements; i++) f.x[i] = wmma::__float_to_tf32(f.x[i]);
}

// stage one BK-chunk of A and W into buffer `buf` via cp.async (no regs)
__device__ __forceinline__ void stage_cp(
    const float* __restrict__ A, const float* __restrict__ W,
    int m0, int n0, int kb, int buf, uint32_t s_base)
{
    const int tid = threadIdx.x;
    const uint32_t s_a = s_base + (uint32_t)buf * 2u * BUF_FL * 4u;
    const uint32_t s_w = s_a + BUF_FL * 4u;
#pragma unroll
    for (int p = 0; p < 4; p++) {
        int idx = p * 256 + tid;            // 0..1023
        int row = idx >> 3;                 // 0..127
        int c4  = (idx & 7) << 2;           // 0..28
        uint32_t soff = (uint32_t)(row * LDS_S + c4) * 4u;
        CP_ASYNC16(s_a + soff, &A[(size_t)(m0 + row) * DIMC + kb * BK + c4]);
        CP_ASYNC16(s_w + soff, &W[(size_t)(n0 + row) * DIMC + kb * BK + c4]);
    }
    CP_COMMIT();
}

__device__ __forceinline__ void gemm_tf32_mainloop(
    const float* __restrict__ A, const float* __restrict__ W,
    int m0, int n0, float* smem, FragC acc[4][2])
{
    const int tid = threadIdx.x;
    const int wid = tid >> 5;
    const int wm  = (wid >> 2) * 64;    // 2 warps in m
    const int wn  = (wid & 3) * 32;     // 4 warps in n
    const uint32_t s_base = smem_u32(smem);

#pragma unroll
    for (int i = 0; i < 4; i++)
#pragma unroll
        for (int j = 0; j < 2; j++) wmma::fill_fragment(acc[i][j], 0.f);

    stage_cp(A, W, m0, n0, 0, 0, s_base);

    const int KT = DIMC / BK;   // 32
    for (int kb = 0; kb < KT; kb++) {
        const int cur = kb & 1;
        if (kb + 1 < KT) {
            stage_cp(A, W, m0, n0, kb + 1, cur ^ 1, s_base);
            CP_WAIT(1);
        } else {
            CP_WAIT(0);
        }
        __syncthreads();   // buffer `cur` ready for all warps

        const float* as = smem + cur * 2 * BUF_FL;
        const float* ws = as + BUF_FL;
#pragma unroll
        for (int ks = 0; ks < BK / 8; ks++) {
            const int k0 = ks * 8;
            FragA a[4]; FragB b[2];
#pragma unroll
            for (int i = 0; i < 4; i++) {
                wmma::load_matrix_sync(a[i], as + (wm + i * 16) * LDS_S + k0, LDS_S);
                cvt_frag_a(a[i]);
            }
#pragma unroll
            for (int j = 0; j < 2; j++) {
                wmma::load_matrix_sync(b[j], ws + (wn + j * 16) * LDS_S + k0, LDS_S);
                cvt_frag_b(b[j]);
            }
#pragma unroll
            for (int i = 0; i < 4; i++)
#pragma unroll
                for (int j = 0; j < 2; j++)
                    wmma::mma_sync(acc[i][j], a[i], b[j], acc[i][j]);
        }
        __syncthreads();   // done reading `cur`; next stage may overwrite
    }
}

__global__ __launch_bounds__(256, 2) void gemm_qkv_tc(
    const float* __restrict__ A, const float* __restrict__ W)
{
    extern __shared__ float smem[];
    const int m0 = blockIdx.y * 128, n0 = blockIdx.x * 128;

    FragC acc[4][2];
    gemm_tf32_mainloop(A, W, m0, n0, smem, acc);

    const int wid = threadIdx.x >> 5;
    const int wm  = (wid >> 2) * 64;
    const int wn  = (wid & 3) * 32;

    const int t = n0 >> 10;                 // 0=q 1=k 2=v (128 | 1024)
    float* dst = (t == 0) ? g_q : ((t == 1) ? g_k : g_v);

#pragma unroll
    for (int i = 0; i < 4; i++) {
        int mrow = m0 + wm + i * 16;
        int bb = mrow >> 11, nn = mrow & (SEQ - 1);
#pragma unroll
        for (int j = 0; j < 2; j++) {
            int col = n0 + wn + j * 16;
            int h = (col & 1023) >> 6, d0 = col & 63;
            if (t == 0) {
#pragma unroll
                for (int e = 0; e < acc[i][j].num_elements; e++)
                    acc[i][j].x[e] *= QSCALE;
            }
            float* p = &dst[(((size_t)(bb * NHEADS + h) * SEQ) + nn) * HDIM + d0];
            wmma::store_matrix_sync(p, acc[i][j], HDIM, wmma::mem_row_major);
        }
    }
}

__global__ __launch_bounds__(256, 2) void gemm_proj_tc(
    const float* __restrict__ W, const float* __restrict__ bias,
    float* __restrict__ out)
{
    extern __shared__ float smem[];
    const int m0 = blockIdx.y * 128, n0 = blockIdx.x * 128;

    FragC acc[4][2];
    gemm_tf32_mainloop(g_attn, W, m0, n0, smem, acc);

    __syncthreads();   // reuse smem as staging
    const int tid  = threadIdx.x;
    const int wid  = tid >> 5;
    const int lane = tid & 31;
    const int wm   = (wid >> 2) * 64;
    const int wn   = (wid & 3) * 32;
    float* stg = smem + wid * (64 * LDS_S);   // 64 rows x 36 floats per warp

#pragma unroll
    for (int i = 0; i < 4; i++)
#pragma unroll
        for (int j = 0; j < 2; j++)
            wmma::store_matrix_sync(stg + (i * 16) * LDS_S + j * 16,
                                    acc[i][j], LDS_S, wmma::mem_row_major);
    __syncwarp();

    // 64 rows x 32 cols per warp = 512 float4; 32 lanes -> 16 each
#pragma unroll
    for (int it = 0; it < 16; it++) {
        int idx = it * 32 + lane;
        int r   = idx >> 3;                // 0..63
        int cc  = (idx & 7) << 2;          // 0..28
        int grow = m0 + wm + r;
        int gcol = n0 + wn + cc;
        float4 v = *(float4*)&stg[r * LDS_S + cc];
        float4 bv = *(const float4*)&bias[gcol];
        v.x += bv.x; v.y += bv.y; v.z += bv.z; v.w += bv.w;
        *(float4*)&out[(size_t)grow * DIMC + gcol] = v;
    }
}

// ============================================================================
// Tensor-core flash attention (unchanged from R6 — known-good).
// ============================================================================
#define APAD 68
#define ATT_SMEM ((64 * APAD + 64 * APAD + 128 * APAD) * 4)   // 69632 B

__device__ __forceinline__ void mma8a(float c[4], const uint32_t a[4],
                                      uint32_t b0, uint32_t b1) {
    mma8(c, a, b0, b1);
}

__global__ __launch_bounds__(256) void attn_tc()
{
    extern __shared__ uint32_t sm[];
    uint32_t* Ks = sm;
    uint32_t* Vt = sm + 64 * APAD;
    uint32_t* Ps = sm + 2 * 64 * APAD;
    float*    Pf = (float*)Ps;

    const int tid  = threadIdx.x;
    const int w    = tid >> 5;
    const int lane = tid & 31;
    const int g    = lane >> 2;
    const int t    = lane & 3;
    const int bh   = blockIdx.y;
    const int q0   = blockIdx.x * 128;
    const float* qp = g_q + (size_t)bh * SEQ * HDIM;
    const float* kp = g_k + (size_t)bh * SEQ * HDIM;
    const float* vp = g_v + (size_t)bh * SEQ * HDIM;

#pragma unroll
    for (int p = 0; p < 8; p++) {
        int idx = p * 256 + tid;
        int row = idx >> 4;
        int c0  = (idx & 15) << 2;
        *(float4*)&Pf[row * APAD + c0] = *(const float4*)&qp[(size_t)(q0 + row) * HDIM + c0];
    }
    __syncthreads();

    const int rlo = w * 16 + g;
    const int rhi = rlo + 8;
    uint32_t qa[8][4];
#pragma unroll
    for (int c = 0; c < 8; c++) {
        qa[c][0] = f2tf32(Pf[rlo * APAD + c * 8 + t] * LOG2E);
        qa[c][1] = f2tf32(Pf[rhi * APAD + c * 8 + t] * LOG2E);
        qa[c][2] = f2tf32(Pf[rlo * APAD + c * 8 + t + 4] * LOG2E);
        qa[c][3] = f2tf32(Pf[rhi * APAD + c * 8 + t + 4] * LOG2E);
    }

    float o[8][4];
#pragma unroll
    for (int nt = 0; nt < 8; nt++)
#pragma unroll
        for (int e = 0; e < 4; e++) o[nt][e] = 0.f;
    float m_lo = -1e30f, m_hi = -1e30f, l_lo = 0.f, l_hi = 0.f;

    for (int j0 = 0; j0 < SEQ; j0 += 64) {
        __syncthreads();
        {
            int r = tid >> 2;
            const float* krow = &kp[(size_t)(j0 + r) * HDIM];
            const float* vrow = &vp[(size_t)(j0 + r) * HDIM];
#pragma unroll
            for (int p = 0; p < 4; p++) {
                int d0 = ((tid & 3) + p * 4) << 2;
                float4 kv = *(const float4*)&krow[d0];
                uint4 ku;
                ku.x = f2tf32(kv.x); ku.y = f2tf32(kv.y);
                ku.z = f2tf32(kv.z); ku.w = f2tf32(kv.w);
                *(uint4*)&Ks[r * APAD + d0] = ku;
                float4 vv = *(const float4*)&vrow[d0];
                Vt[(d0 + 0) * APAD + r] = f2tf32(vv.x);
                Vt[(d0 + 1) * APAD + r] = f2tf32(vv.y);
                Vt[(d0 + 2) * APAD + r] = f2tf32(vv.z);
                Vt[(d0 + 3) * APAD + r] = f2tf32(vv.w);
            }
        }
        __syncthreads();

        float s[8][4];
#pragma unroll
        for (int nt = 0; nt < 8; nt++)
#pragma unroll
            for (int e = 0; e < 4; e++) s[nt][e] = 0.f;
#pragma unroll
        for (int c = 0; c < 8; c++) {
#pragma unroll
            for (int nt = 0; nt < 8; nt++) {
                uint32_t b0 = Ks[(nt * 8 + g) * APAD + c * 8 + t];
                uint32_t b1 = Ks[(nt * 8 + g) * APAD + c * 8 + t + 4];
                mma8(s[nt], qa[c], b0, b1);
            }
        }

        float tl = -1e30f, th = -1e30f;
#pragma unroll
        for (int nt = 0; nt < 8; nt++) {
            tl = fmaxf(tl, fmaxf(s[nt][0], s[nt][1]));
            th = fmaxf(th, fmaxf(s[nt][2], s[nt][3]));
        }
        tl = fmaxf(tl, __shfl_xor_sync(0xffffffffu, tl, 1));
        tl = fmaxf(tl, __shfl_xor_sync(0xffffffffu, tl, 2));
        th = fmaxf(th, __shfl_xor_sync(0xffffffffu, th, 1));
        th = fmaxf(th, __shfl_xor_sync(0xffffffffu, th, 2));
        float mn_lo = fmaxf(m_lo, tl), mn_hi = fmaxf(m_hi, th);
        float cr_lo = ex2(m_lo - mn_lo), cr_hi = ex2(m_hi - mn_hi);

        float rs_lo = 0.f, rs_hi = 0.f;
#pragma unroll
        for (int nt = 0; nt < 8; nt++) {
            uint32_t p0 = f2tf32(ex2(s[nt][0] - mn_lo));
            uint32_t p1 = f2tf32(ex2(s[nt][1] - mn_lo));
            uint32_t p2 = f2tf32(ex2(s[nt][2] - mn_hi));
            uint32_t p3 = f2tf32(ex2(s[nt][3] - mn_hi));
            rs_lo += __uint_as_float(p0) + __uint_as_float(p1);
            rs_hi += __uint_as_float(p2) + __uint_as_float(p3);
            Ps[rlo * APAD + nt * 8 + 2 * t]     = p0;
            Ps[rlo * APAD + nt * 8 + 2 * t + 1] = p1;
            Ps[rhi * APAD + nt * 8 + 2 * t]     = p2;
            Ps[rhi * APAD + nt * 8 + 2 * t + 1] = p3;
        }
        rs_lo += __shfl_xor_sync(0xffffffffu, rs_lo, 1);
        rs_lo += __shfl_xor_sync(0xffffffffu, rs_lo, 2);
        rs_hi += __shfl_xor_sync(0xffffffffu, rs_hi, 1);
        rs_hi += __shfl_xor_sync(0xffffffffu, rs_hi, 2);
        l_lo = l_lo * cr_lo + rs_lo;
        l_hi = l_hi * cr_hi + rs_hi;
        m_lo = mn_lo; m_hi = mn_hi;
#pragma unroll
        for (int nt = 0; nt < 8; nt++) {
            o[nt][0] *= cr_lo; o[nt][1] *= cr_lo;
            o[nt][2] *= cr_hi; o[nt][3] *= cr_hi;
        }
        __syncwarp();

        uint32_t pa[8][4];
#pragma unroll
        for (int c = 0; c < 8; c++) {
            pa[c][0] = Ps[rlo * APAD + c * 8 + t];
            pa[c][1] = Ps[rhi * APAD + c * 8 + t];
            pa[c][2] = Ps[rlo * APAD + c * 8 + t + 4];
            pa[c][3] = Ps[rhi * APAD + c * 8 + t + 4];
        }

#pragma unroll
        for (int c = 0; c < 8; c++) {
#pragma unroll
            for (int nt = 0; nt < 8; nt++) {
                uint32_t b0 = Vt[(nt * 8 + g) * APAD + c * 8 + t];
                uint32_t b1 = Vt[(nt * 8 + g) * APAD + c * 8 + t + 4];
                mma8(o[nt], pa[c], b0, b1);
            }
        }
    }

    const int b = bh >> 4;
    const int h = bh & 15;
    float inv_lo = 1.f / l_lo, inv_hi = 1.f / l_hi;
    size_t base_lo = ((size_t)b * SEQ + q0 + rlo) * DIMC + h * HDIM;
    size_t base_hi = ((size_t)b * SEQ + q0 + rhi) * DIMC + h * HDIM;
#pragma unroll
    for (int nt = 0; nt < 8; nt++) {
        float2 vlo = make_float2(o[nt][0] * inv_lo, o[nt][1] * inv_lo);
        float2 vhi = make_float2(o[nt][2] * inv_hi, o[nt][3] * inv_hi);
        *(float2*)&g_attn[base_lo + nt * 8 + 2 * t] = vlo;
        *(float2*)&g_attn[base_hi + nt * 8 + 2 * t] = vhi;
    }
}

// ============================================================================
// launch
// ============================================================================
extern "C" void kernel_launch(void* const* d_in, const int* in_sizes, int n_in,
                              void* d_out, int out_size)
{
    const float* x     = (const float*)d_in[0];
    const float* Wqkv  = (const float*)d_in[1];
    const float* Wproj = (const float*)d_in[2];
    const float* bproj = (const float*)d_in[3];
    float* out = (float*)d_out;

    cudaFuncSetAttribute(gemm_qkv_tc,
                         cudaFuncAttributeMaxDynamicSharedMemorySize, GEMM_SMEM);
    cudaFuncSetAttribute(gemm_proj_tc,
                         cudaFuncAttributeMaxDynamicSharedMemorySize, GEMM_SMEM);
    cudaFuncSetAttribute(attn_tc,
                         cudaFuncAttributeMaxDynamicSharedMemorySize, ATT_SMEM);

    gemm_qkv_tc<<<dim3(3 * DIMC / 128, MTOT / 128), 256, GEMM_SMEM>>>(x, Wqkv);
    attn_tc<<<dim3(SEQ / 128, BATCH * NHEADS), 256, ATT_SMEM>>>();
    gemm_proj_tc<<<dim3(DIMC / 128, MTOT / 128), 256, GEMM_SMEM>>>(Wproj, bproj, out);
}